// round 6
// baseline (speedup 1.0000x reference)
#include <cuda_runtime.h>
#include <cuda_bf16.h>
#include <cstdint>

// Problem constants
constexpr int cB = 8;
constexpr int cN = 1024;
constexpr int cC = 640;
constexpr int cH = 8;
constexpr int cD = 80;
constexpr int cR = 3;
constexpr int cInner = cH * cD;        // 640
constexpr int cM = cB * cN;            // 8192
constexpr float SCALE = 0.11180339887498949f;  // 80^-0.5

// Scratch
__device__ float g_q[cM * cInner];
__device__ float g_k[cM * cInner];
__device__ float g_v[cM * cInner];
__device__ float g_ao[cM * cInner];

// ---------------------------------------------------------------------------
// helpers
// ---------------------------------------------------------------------------
__device__ __forceinline__ uint32_t smem_u32(const void* p) {
    uint32_t a;
    asm("{ .reg .u64 t; cvta.to.shared.u64 t, %1; cvt.u32.u64 %0, t; }"
        : "=r"(a) : "l"(p));
    return a;
}
__device__ __forceinline__ uint32_t tf32r(float x) {
    uint32_t r;
    asm("cvt.rna.tf32.f32 %0, %1;" : "=r"(r) : "f"(x));
    return r;
}
__device__ __forceinline__ float tf32rf(float x) {
    return __uint_as_float(tf32r(x));
}
__device__ __forceinline__ void mma_tf32(float* c, const uint32_t* a,
                                         uint32_t b0, uint32_t b1) {
    asm volatile(
        "mma.sync.aligned.m16n8k8.row.col.f32.tf32.tf32.f32 "
        "{%0,%1,%2,%3}, {%4,%5,%6,%7}, {%8,%9}, {%0,%1,%2,%3};"
        : "+f"(c[0]), "+f"(c[1]), "+f"(c[2]), "+f"(c[3])
        : "r"(a[0]), "r"(a[1]), "r"(a[2]), "r"(a[3]), "r"(b0), "r"(b1));
}
__device__ __forceinline__ void cp_async16(uint32_t dst, const void* src) {
    asm volatile("cp.async.ca.shared.global [%0], [%1], 16;" :: "r"(dst), "l"(src));
}
__device__ __forceinline__ void cp_commit() {
    asm volatile("cp.async.commit_group;" ::: "memory");
}
template <int N>
__device__ __forceinline__ void cp_wait() {
    asm volatile("cp.async.wait_group %0;" :: "n"(N) : "memory");
}

// ---------------------------------------------------------------------------
// tf32 tensor-core GEMM with cp.async double-buffered pipeline (round-5 win).
// C[M,Nc] = A[M,K] * B[Nc,K]^T (+bias). 128x128 tile, BK=32, 8 warps (2x4).
// ---------------------------------------------------------------------------
constexpr int GP2  = 36;                    // smem row pitch (words)
constexpr int GBUF = 128 * GP2;             // words per buffer per operand
constexpr int GEMM_SMEM = 4 * GBUF * 4;     // 73728 B

__global__ __launch_bounds__(256, 2) void gemm_tf32(
    const float* __restrict__ A, const float* __restrict__ Bm,
    float* __restrict__ C, const float* __restrict__ bias,
    int M, int Nc, int K)
{
    extern __shared__ float gsm[];
    float* As = gsm;
    float* Bs = gsm + 2 * GBUF;

    const int tid  = threadIdx.x;
    const int wid  = tid >> 5;
    const int lane = tid & 31;
    const int gid  = lane >> 2;
    const int tig  = lane & 3;
    const int wm   = (wid & 1) * 64;
    const int wn   = (wid >> 1) * 32;

    const int srow = tid >> 1;
    const int skc  = (tid & 1) * 16;

    const float* Ap = A  + (size_t)(blockIdx.y * 128 + srow) * K + skc;
    const float* Bp = Bm + (size_t)(blockIdx.x * 128 + srow) * K + skc;
    const uint32_t sA = smem_u32(As) + (srow * GP2 + skc) * 4;
    const uint32_t sB = smem_u32(Bs) + (srow * GP2 + skc) * 4;
    const uint32_t bufB = GBUF * 4;

    float acc[4][4][4];
#pragma unroll
    for (int mi = 0; mi < 4; mi++)
#pragma unroll
        for (int nj = 0; nj < 4; nj++)
#pragma unroll
            for (int j = 0; j < 4; j++) acc[mi][nj][j] = 0.f;

    const int nk = K >> 5;

#pragma unroll
    for (int i = 0; i < 4; i++) {
        cp_async16(sA + i * 16, Ap + i * 4);
        cp_async16(sB + i * 16, Bp + i * 4);
    }
    cp_commit();

#pragma unroll 1
    for (int t = 0; t < nk; t++) {
        if (t + 1 < nk) {
            const uint32_t bo = (uint32_t)((t + 1) & 1) * bufB;
            const float* ap = Ap + (t + 1) * 32;
            const float* bp = Bp + (t + 1) * 32;
#pragma unroll
            for (int i = 0; i < 4; i++) {
                cp_async16(sA + bo + i * 16, ap + i * 4);
                cp_async16(sB + bo + i * 16, bp + i * 4);
            }
            cp_commit();
            cp_wait<1>();
        } else {
            cp_wait<0>();
        }
        __syncthreads();

        const float* Ab = As + (t & 1) * GBUF;
        const float* Bb = Bs + (t & 1) * GBUF;

#pragma unroll
        for (int ks = 0; ks < 4; ks++) {
            uint32_t af[4][4];
#pragma unroll
            for (int mi = 0; mi < 4; mi++) {
                const float* p0 = Ab + (wm + mi * 16 + gid) * GP2 + ks * 8 + tig;
                af[mi][0] = tf32r(p0[0]);
                af[mi][1] = tf32r(p0[8 * GP2]);
                af[mi][2] = tf32r(p0[4]);
                af[mi][3] = tf32r(p0[8 * GP2 + 4]);
            }
#pragma unroll
            for (int nj = 0; nj < 4; nj++) {
                const float* p = Bb + (wn + nj * 8 + gid) * GP2 + ks * 8 + tig;
                const uint32_t b0 = tf32r(p[0]);
                const uint32_t b1 = tf32r(p[4]);
#pragma unroll
                for (int mi = 0; mi < 4; mi++)
                    mma_tf32(acc[mi][nj], af[mi], b0, b1);
            }
        }
        __syncthreads();
    }

#pragma unroll
    for (int nj = 0; nj < 4; nj++) {
        const int col = blockIdx.x * 128 + wn + nj * 8 + tig * 2;
        const float ba0 = bias ? bias[col]     : 0.f;
        const float ba1 = bias ? bias[col + 1] : 0.f;
#pragma unroll
        for (int mi = 0; mi < 4; mi++) {
            const int row = blockIdx.y * 128 + wm + mi * 16 + gid;
            float* cp = C + (size_t)row * Nc + col;
            *(float2*)cp = make_float2(acc[mi][nj][0] + ba0, acc[mi][nj][1] + ba1);
            *(float2*)(cp + (size_t)8 * Nc) =
                make_float2(acc[mi][nj][2] + ba0, acc[mi][nj][3] + ba1);
        }
    }
}

// ---------------------------------------------------------------------------
// Flash attention, mma.sync tf32. 128q x 128k tiles, 256 threads (8 warps),
// warp w owns query rows [w*16, w*16+16).  K stays ROW-MAJOR in smem (the
// col-major B operand of QK^T is row-major K — no transpose needed), so K/V
// staging is pure 16B copies via cp.async, double-buffered across the
// 24-tile loop.  tf32 rounding at fragment load (same values as staging-time
// rounding).  Smem: Qs[128][84] + 2 x (Ks[128][84] + Vs[128][88]) = 219136 B.
// ---------------------------------------------------------------------------
constexpr int QSP = 84;                   // Qs/Ks pitch (gid*84+tig: 32 banks)
constexpr int VSP = 88;                   // Vs pitch (tig*88+gid: 32 banks)
constexpr int KVW = 128 * QSP + 128 * VSP;        // words per KV buffer = 22016
constexpr int SM_KV = 128 * QSP;                  // Qs size = 10752 words
constexpr int ATTN_SMEM = (SM_KV + 2 * KVW) * 4;  // 219136 bytes

__global__ __launch_bounds__(256, 1) void attn_mma(const int* __restrict__ ctx)
{
    extern __shared__ float sm[];
    float* Qs = sm;

    const int tid  = threadIdx.x;
    const int wid  = tid >> 5;
    const int lane = tid & 31;
    const int gid  = lane >> 2;
    const int tig  = lane & 3;
    const int m0   = wid * 16;

    const int qt = blockIdx.x, h = blockIdx.y, b = blockIdx.z;

    const int r0 = tid >> 1;           // 0..127
    const int d0 = (tid & 1) * 40;     // 0/40

    // byte addresses for cp.async staging (16B-aligned: 84*4=336, 88*4=352)
    const uint32_t sKV0 = smem_u32(sm + SM_KV);
    const uint32_t ksOff = (uint32_t)(r0 * QSP + d0) * 4;
    const uint32_t vsOff = (uint32_t)(128 * QSP + r0 * VSP + d0) * 4;

    const int frame0 = ctx[b * cR + 0];
    const int frame1 = ctx[b * cR + 1];
    const int frame2 = ctx[b * cR + 2];

    // ---- stage Q (SCALE folded, tf32-rounded at stage; read once) ----
    {
        const float* qp = g_q + (size_t)(b * cN + qt * 128 + r0) * cInner + h * cD + d0;
        float* qs = Qs + r0 * QSP + d0;
#pragma unroll
        for (int i = 0; i < 10; i++) {
            float4 v = *(const float4*)(qp + i * 4);
            qs[i * 4 + 0] = tf32rf(v.x * SCALE);
            qs[i * 4 + 1] = tf32rf(v.y * SCALE);
            qs[i * 4 + 2] = tf32rf(v.z * SCALE);
            qs[i * 4 + 3] = tf32rf(v.w * SCALE);
        }
    }

    // ---- prologue: stage KV tile 0 into buffer 0 ----
    {
        const size_t gof = (size_t)(frame0 * cN + r0) * cInner + h * cD + d0;
        const float* kp = g_k + gof;
        const float* vp = g_v + gof;
#pragma unroll
        for (int i = 0; i < 10; i++) {
            cp_async16(sKV0 + ksOff + i * 16, kp + i * 4);
            cp_async16(sKV0 + vsOff + i * 16, vp + i * 4);
        }
        cp_commit();
    }
    __syncthreads();   // Qs visible to all warps

    // ---- Q A-fragments in registers (reused for all 24 KV tiles) ----
    uint32_t qa[10][4];
#pragma unroll
    for (int k = 0; k < 10; k++) {
        qa[k][0] = __float_as_uint(Qs[(m0 + gid) * QSP + k * 8 + tig]);
        qa[k][1] = __float_as_uint(Qs[(m0 + gid + 8) * QSP + k * 8 + tig]);
        qa[k][2] = __float_as_uint(Qs[(m0 + gid) * QSP + k * 8 + tig + 4]);
        qa[k][3] = __float_as_uint(Qs[(m0 + gid + 8) * QSP + k * 8 + tig + 4]);
    }

    float o[10][4];
#pragma unroll
    for (int n = 0; n < 10; n++)
#pragma unroll
        for (int j = 0; j < 4; j++) o[n][j] = 0.f;
    float mlo = -1e30f, mhi = -1e30f, llo = 0.f, lhi = 0.f;

    const int sh1 = (lane & 28) | (tig >> 1);
    const int sh2 = sh1 + 2;
    const bool odd = (tig & 1);

#pragma unroll 1
    for (int t = 0; t < 24; t++) {
        // ---- issue cp.async for tile t+1 into the other buffer ----
        if (t + 1 < 24) {
            const int tn = t + 1;
            const int frame = (tn >> 3) == 0 ? frame0 : (tn >> 3) == 1 ? frame1 : frame2;
            const int kb = (tn * 128) & (cN - 1);
            const size_t gof = (size_t)(frame * cN + kb + r0) * cInner + h * cD + d0;
            const float* kp = g_k + gof;
            const float* vp = g_v + gof;
            const uint32_t bo = sKV0 + (uint32_t)((tn & 1) * KVW) * 4;
#pragma unroll
            for (int i = 0; i < 10; i++) {
                cp_async16(bo + ksOff + i * 16, kp + i * 4);
                cp_async16(bo + vsOff + i * 16, vp + i * 4);
            }
            cp_commit();
            cp_wait<1>();
        } else {
            cp_wait<0>();
        }
        __syncthreads();   // tile t visible to all warps

        const float* Ks = sm + SM_KV + (t & 1) * KVW;
        const float* Vs = Ks + 128 * QSP;

        // ---- S = Q K^T : 16 n-tiles x 10 k-steps (B = row-major K) ----
        float s[16][4];
#pragma unroll
        for (int n = 0; n < 16; n++)
#pragma unroll
            for (int j = 0; j < 4; j++) s[n][j] = 0.f;

#pragma unroll
        for (int n = 0; n < 16; n++) {
            const float* krow = Ks + (n * 8 + gid) * QSP + tig;
#pragma unroll
            for (int k = 0; k < 10; k++) {
                uint32_t b0 = tf32r(krow[k * 8]);
                uint32_t b1 = tf32r(krow[k * 8 + 4]);
                mma_tf32(s[n], qa[k], b0, b1);
            }
        }

        // ---- online softmax (rows live in-warp) ----
        float mx0 = -1e30f, mx1 = -1e30f;
#pragma unroll
        for (int n = 0; n < 16; n++) {
            mx0 = fmaxf(mx0, fmaxf(s[n][0], s[n][1]));
            mx1 = fmaxf(mx1, fmaxf(s[n][2], s[n][3]));
        }
        mx0 = fmaxf(mx0, __shfl_xor_sync(0xffffffffu, mx0, 1));
        mx0 = fmaxf(mx0, __shfl_xor_sync(0xffffffffu, mx0, 2));
        mx1 = fmaxf(mx1, __shfl_xor_sync(0xffffffffu, mx1, 1));
        mx1 = fmaxf(mx1, __shfl_xor_sync(0xffffffffu, mx1, 2));

        const float mn0 = fmaxf(mlo, mx0);
        const float mn1 = fmaxf(mhi, mx1);
        const float cf0 = __expf(mlo - mn0);
        const float cf1 = __expf(mhi - mn1);
        mlo = mn0; mhi = mn1;

        float rs0 = 0.f, rs1 = 0.f;
#pragma unroll
        for (int n = 0; n < 16; n++) {
            s[n][0] = __expf(s[n][0] - mn0); rs0 += s[n][0];
            s[n][1] = __expf(s[n][1] - mn0); rs0 += s[n][1];
            s[n][2] = __expf(s[n][2] - mn1); rs1 += s[n][2];
            s[n][3] = __expf(s[n][3] - mn1); rs1 += s[n][3];
        }
        rs0 += __shfl_xor_sync(0xffffffffu, rs0, 1);
        rs0 += __shfl_xor_sync(0xffffffffu, rs0, 2);
        rs1 += __shfl_xor_sync(0xffffffffu, rs1, 1);
        rs1 += __shfl_xor_sync(0xffffffffu, rs1, 2);
        llo = llo * cf0 + rs0;
        lhi = lhi * cf1 + rs1;

#pragma unroll
        for (int n = 0; n < 10; n++) {
            o[n][0] *= cf0; o[n][1] *= cf0;
            o[n][2] *= cf1; o[n][3] *= cf1;
        }

        // ---- O += P V : 16 k-tiles x 10 n-tiles ----
#pragma unroll
        for (int kt = 0; kt < 16; kt++) {
            float v00 = __shfl_sync(0xffffffffu, s[kt][0], sh1);
            float v01 = __shfl_sync(0xffffffffu, s[kt][1], sh1);
            float v02 = __shfl_sync(0xffffffffu, s[kt][0], sh2);
            float v03 = __shfl_sync(0xffffffffu, s[kt][1], sh2);
            float v10 = __shfl_sync(0xffffffffu, s[kt][2], sh1);
            float v11 = __shfl_sync(0xffffffffu, s[kt][3], sh1);
            float v12 = __shfl_sync(0xffffffffu, s[kt][2], sh2);
            float v13 = __shfl_sync(0xffffffffu, s[kt][3], sh2);
            uint32_t pa[4];
            pa[0] = tf32r(odd ? v01 : v00);
            pa[1] = tf32r(odd ? v11 : v10);
            pa[2] = tf32r(odd ? v03 : v02);
            pa[3] = tf32r(odd ? v13 : v12);

            const float* vrow0 = Vs + (kt * 8 + tig) * VSP + gid;
            const float* vrow1 = Vs + (kt * 8 + tig + 4) * VSP + gid;
#pragma unroll
            for (int n = 0; n < 10; n++) {
                uint32_t b0 = tf32r(vrow0[n * 8]);
                uint32_t b1 = tf32r(vrow1[n * 8]);
                mma_tf32(o[n], pa, b0, b1);
            }
        }
        __syncthreads();   // all warps done with buffer (t&1) before overwrite
    }

    // ---- epilogue ----
    const float inv0 = 1.f / llo;
    const float inv1 = 1.f / lhi;
    float* op0 = g_ao + (size_t)(b * cN + qt * 128 + m0 + gid) * cInner + h * cD;
    float* op1 = op0 + (size_t)8 * cInner;
#pragma unroll
    for (int n = 0; n < 10; n++) {
        *(float2*)(op0 + n * 8 + tig * 2) = make_float2(o[n][0] * inv0, o[n][1] * inv0);
        *(float2*)(op1 + n * 8 + tig * 2) = make_float2(o[n][2] * inv1, o[n][3] * inv1);
    }
}

// ---------------------------------------------------------------------------
extern "C" void kernel_launch(void* const* d_in, const int* in_sizes, int n_in,
                              void* d_out, int out_size)
{
    const float* x   = (const float*)d_in[0];
    const float* Wq  = (const float*)d_in[1];
    const float* Wk  = (const float*)d_in[2];
    const float* Wv  = (const float*)d_in[3];
    const float* Wo  = (const float*)d_in[4];
    const float* bo  = (const float*)d_in[5];
    const int*   ctx = (const int*)d_in[6];
    float* out = (float*)d_out;

    float* gq;  cudaGetSymbolAddress((void**)&gq, g_q);
    float* gk;  cudaGetSymbolAddress((void**)&gk, g_k);
    float* gv;  cudaGetSymbolAddress((void**)&gv, g_v);
    float* gao; cudaGetSymbolAddress((void**)&gao, g_ao);

    static bool attr_set = false;
    if (!attr_set) {
        cudaFuncSetAttribute(attn_mma,
                             cudaFuncAttributeMaxDynamicSharedMemorySize,
                             ATTN_SMEM);
        cudaFuncSetAttribute(gemm_tf32,
                             cudaFuncAttributeMaxDynamicSharedMemorySize,
                             GEMM_SMEM);
        attr_set = true;
    }

    const dim3 gg(cInner / 128, cM / 128);   // (5, 64)
    gemm_tf32<<<gg, 256, GEMM_SMEM>>>(x, Wq, gq, nullptr, cM, cInner, cC);
    gemm_tf32<<<gg, 256, GEMM_SMEM>>>(x, Wk, gk, nullptr, cM, cInner, cC);
    gemm_tf32<<<gg, 256, GEMM_SMEM>>>(x, Wv, gv, nullptr, cM, cInner, cC);

    attn_mma<<<dim3(8, 8, 8), 256, ATTN_SMEM>>>(ctx);

    gemm_tf32<<<dim3(cC / 128, cM / 128), 256, GEMM_SMEM>>>(gao, Wo, out, bo, cM, cC, cInner);
}

// round 7
// speedup vs baseline: 1.1115x; 1.1115x over previous
#include <cuda_runtime.h>
#include <cuda_bf16.h>
#include <cstdint>

// Problem constants
constexpr int cB = 8;
constexpr int cN = 1024;
constexpr int cC = 640;
constexpr int cH = 8;
constexpr int cD = 80;
constexpr int cR = 3;
constexpr int cInner = cH * cD;        // 640
constexpr int cM = cB * cN;            // 8192
constexpr float SCALE = 0.11180339887498949f;  // 80^-0.5

// Scratch
__device__ float g_q[cM * cInner];
__device__ float g_k[cM * cInner];
__device__ float g_v[cM * cInner];
__device__ float g_ao[cM * cInner];

// ---------------------------------------------------------------------------
// helpers
// ---------------------------------------------------------------------------
__device__ __forceinline__ uint32_t smem_u32(const void* p) {
    uint32_t a;
    asm("{ .reg .u64 t; cvta.to.shared.u64 t, %1; cvt.u32.u64 %0, t; }"
        : "=r"(a) : "l"(p));
    return a;
}
__device__ __forceinline__ uint32_t tf32r(float x) {
    uint32_t r;
    asm("cvt.rna.tf32.f32 %0, %1;" : "=r"(r) : "f"(x));
    return r;
}
__device__ __forceinline__ float tf32rf(float x) {
    return __uint_as_float(tf32r(x));
}
__device__ __forceinline__ void mma_tf32(float* c, const uint32_t* a,
                                         uint32_t b0, uint32_t b1) {
    asm volatile(
        "mma.sync.aligned.m16n8k8.row.col.f32.tf32.tf32.f32 "
        "{%0,%1,%2,%3}, {%4,%5,%6,%7}, {%8,%9}, {%0,%1,%2,%3};"
        : "+f"(c[0]), "+f"(c[1]), "+f"(c[2]), "+f"(c[3])
        : "r"(a[0]), "r"(a[1]), "r"(a[2]), "r"(a[3]), "r"(b0), "r"(b1));
}
__device__ __forceinline__ void cp_async16(uint32_t dst, const void* src) {
    asm volatile("cp.async.ca.shared.global [%0], [%1], 16;" :: "r"(dst), "l"(src));
}
__device__ __forceinline__ void cp_commit() {
    asm volatile("cp.async.commit_group;" ::: "memory");
}
template <int N>
__device__ __forceinline__ void cp_wait() {
    asm volatile("cp.async.wait_group %0;" :: "n"(N) : "memory");
}

// ---------------------------------------------------------------------------
// tf32 tensor-core GEMM, cp.async double-buffered (round-5 proven core).
// gridDim.z selects among up to 3 (B, C) pairs -> fused QKV projection in one
// launch (960 CTAs = good wave packing vs 3 x 1.08 waves).
// doRound: epilogue writes tf32rf(val * pm) -- pre-rounds producer data for
// the attention kernel (pm = SCALE for q when z==0, 1 otherwise).
// ---------------------------------------------------------------------------
constexpr int GP2  = 36;                    // smem row pitch (words)
constexpr int GBUF = 128 * GP2;             // words per buffer per operand
constexpr int GEMM_SMEM = 4 * GBUF * 4;     // 73728 B

__global__ __launch_bounds__(256, 2) void gemm_tf32(
    const float* __restrict__ A,
    const float* __restrict__ B0, const float* __restrict__ B1,
    const float* __restrict__ B2,
    float* __restrict__ C0, float* __restrict__ C1, float* __restrict__ C2,
    const float* __restrict__ bias,
    int M, int Nc, int K, float pm, int doRound)
{
    extern __shared__ float gsm[];
    float* As = gsm;
    float* Bs = gsm + 2 * GBUF;

    const int z = blockIdx.z;
    const float* Bm = (z == 0) ? B0 : (z == 1) ? B1 : B2;
    float* C = (z == 0) ? C0 : (z == 1) ? C1 : C2;
    const float pmz = (z == 0) ? pm : 1.0f;

    const int tid  = threadIdx.x;
    const int wid  = tid >> 5;
    const int lane = tid & 31;
    const int gid  = lane >> 2;
    const int tig  = lane & 3;
    const int wm   = (wid & 1) * 64;
    const int wn   = (wid >> 1) * 32;

    const int srow = tid >> 1;
    const int skc  = (tid & 1) * 16;

    const float* Ap = A  + (size_t)(blockIdx.y * 128 + srow) * K + skc;
    const float* Bp = Bm + (size_t)(blockIdx.x * 128 + srow) * K + skc;
    const uint32_t sA = smem_u32(As) + (srow * GP2 + skc) * 4;
    const uint32_t sB = smem_u32(Bs) + (srow * GP2 + skc) * 4;
    const uint32_t bufB = GBUF * 4;

    float acc[4][4][4];
#pragma unroll
    for (int mi = 0; mi < 4; mi++)
#pragma unroll
        for (int nj = 0; nj < 4; nj++)
#pragma unroll
            for (int j = 0; j < 4; j++) acc[mi][nj][j] = 0.f;

    const int nk = K >> 5;

#pragma unroll
    for (int i = 0; i < 4; i++) {
        cp_async16(sA + i * 16, Ap + i * 4);
        cp_async16(sB + i * 16, Bp + i * 4);
    }
    cp_commit();

#pragma unroll 1
    for (int t = 0; t < nk; t++) {
        if (t + 1 < nk) {
            const uint32_t bo = (uint32_t)((t + 1) & 1) * bufB;
            const float* ap = Ap + (t + 1) * 32;
            const float* bp = Bp + (t + 1) * 32;
#pragma unroll
            for (int i = 0; i < 4; i++) {
                cp_async16(sA + bo + i * 16, ap + i * 4);
                cp_async16(sB + bo + i * 16, bp + i * 4);
            }
            cp_commit();
            cp_wait<1>();
        } else {
            cp_wait<0>();
        }
        __syncthreads();

        const float* Ab = As + (t & 1) * GBUF;
        const float* Bb = Bs + (t & 1) * GBUF;

#pragma unroll
        for (int ks = 0; ks < 4; ks++) {
            uint32_t af[4][4];
#pragma unroll
            for (int mi = 0; mi < 4; mi++) {
                const float* p0 = Ab + (wm + mi * 16 + gid) * GP2 + ks * 8 + tig;
                af[mi][0] = tf32r(p0[0]);
                af[mi][1] = tf32r(p0[8 * GP2]);
                af[mi][2] = tf32r(p0[4]);
                af[mi][3] = tf32r(p0[8 * GP2 + 4]);
            }
#pragma unroll
            for (int nj = 0; nj < 4; nj++) {
                const float* p = Bb + (wn + nj * 8 + gid) * GP2 + ks * 8 + tig;
                const uint32_t b0 = tf32r(p[0]);
                const uint32_t b1 = tf32r(p[4]);
#pragma unroll
                for (int mi = 0; mi < 4; mi++)
                    mma_tf32(acc[mi][nj], af[mi], b0, b1);
            }
        }
        __syncthreads();
    }

#pragma unroll
    for (int nj = 0; nj < 4; nj++) {
        const int col = blockIdx.x * 128 + wn + nj * 8 + tig * 2;
        const float ba0 = bias ? bias[col]     : 0.f;
        const float ba1 = bias ? bias[col + 1] : 0.f;
#pragma unroll
        for (int mi = 0; mi < 4; mi++) {
            const int row = blockIdx.y * 128 + wm + mi * 16 + gid;
            float* cp = C + (size_t)row * Nc + col;
            float v00 = acc[mi][nj][0] + ba0;
            float v01 = acc[mi][nj][1] + ba1;
            float v10 = acc[mi][nj][2] + ba0;
            float v11 = acc[mi][nj][3] + ba1;
            if (doRound) {
                v00 = tf32rf(v00 * pmz); v01 = tf32rf(v01 * pmz);
                v10 = tf32rf(v10 * pmz); v11 = tf32rf(v11 * pmz);
            }
            *(float2*)cp = make_float2(v00, v01);
            *(float2*)(cp + (size_t)8 * Nc) = make_float2(v10, v11);
        }
    }
}

// ---------------------------------------------------------------------------
// Flash attention, mma.sync tf32. 128q x 128k tiles, 256 threads (8 warps).
// g_q/g_k/g_v are PRE-ROUNDED tf32 values (and g_q pre-scaled), so all
// staging is pure cp.async byte copies and the inner loops are LDS+HMMA only
// (no CVT -- the round-6 regression).  KV double-buffered across the 24-tile
// loop.  Smem: Qs[128][84] + 2 x (Ks[128][84] + Vs[128][88]) = 219136 B.
// ---------------------------------------------------------------------------
constexpr int QSP = 84;                   // Qs/Ks pitch (gid*84+tig: 32 banks)
constexpr int VSP = 88;                   // Vs pitch (tig*88+gid: 32 banks)
constexpr int KVW = 128 * QSP + 128 * VSP;        // words per KV buffer
constexpr int SM_KV = 128 * QSP;                  // Qs words
constexpr int ATTN_SMEM = (SM_KV + 2 * KVW) * 4;  // 219136 bytes

__global__ __launch_bounds__(256, 1) void attn_mma(const int* __restrict__ ctx)
{
    extern __shared__ float sm[];
    float* Qs = sm;

    const int tid  = threadIdx.x;
    const int wid  = tid >> 5;
    const int lane = tid & 31;
    const int gid  = lane >> 2;
    const int tig  = lane & 3;
    const int m0   = wid * 16;

    const int qt = blockIdx.x, h = blockIdx.y, b = blockIdx.z;

    const int r0 = tid >> 1;           // 0..127
    const int d0 = (tid & 1) * 40;     // 0/40

    const uint32_t sQ   = smem_u32(sm);
    const uint32_t sKV0 = smem_u32(sm + SM_KV);
    const uint32_t rowQ = (uint32_t)(r0 * QSP + d0) * 4;          // Qs/Ks offset
    const uint32_t rowV = (uint32_t)(128 * QSP + r0 * VSP + d0) * 4;

    const int frame0 = ctx[b * cR + 0];
    const int frame1 = ctx[b * cR + 1];
    const int frame2 = ctx[b * cR + 2];

    // ---- prologue: async-stage Q (group 0), then KV tile 0 (group 1) ----
    {
        const float* qp = g_q + (size_t)(b * cN + qt * 128 + r0) * cInner + h * cD + d0;
#pragma unroll
        for (int i = 0; i < 10; i++)
            cp_async16(sQ + rowQ + i * 16, qp + i * 4);
        cp_commit();                                   // G0 = Q

        const size_t gof = (size_t)(frame0 * cN + r0) * cInner + h * cD + d0;
        const float* kp = g_k + gof;
        const float* vp = g_v + gof;
#pragma unroll
        for (int i = 0; i < 10; i++) {
            cp_async16(sKV0 + rowQ + i * 16, kp + i * 4);
            cp_async16(sKV0 + rowV + i * 16, vp + i * 4);
        }
        cp_commit();                                   // G1 = KV0
    }
    cp_wait<1>();      // Q complete (KV0 may still be in flight)
    __syncthreads();

    // ---- Q A-fragments in registers (pre-scaled, pre-rounded) ----
    uint32_t qa[10][4];
#pragma unroll
    for (int k = 0; k < 10; k++) {
        qa[k][0] = __float_as_uint(Qs[(m0 + gid) * QSP + k * 8 + tig]);
        qa[k][1] = __float_as_uint(Qs[(m0 + gid + 8) * QSP + k * 8 + tig]);
        qa[k][2] = __float_as_uint(Qs[(m0 + gid) * QSP + k * 8 + tig + 4]);
        qa[k][3] = __float_as_uint(Qs[(m0 + gid + 8) * QSP + k * 8 + tig + 4]);
    }

    float o[10][4];
#pragma unroll
    for (int n = 0; n < 10; n++)
#pragma unroll
        for (int j = 0; j < 4; j++) o[n][j] = 0.f;
    float mlo = -1e30f, mhi = -1e30f, llo = 0.f, lhi = 0.f;

    const int sh1 = (lane & 28) | (tig >> 1);
    const int sh2 = sh1 + 2;
    const bool odd = (tig & 1);

#pragma unroll 1
    for (int t = 0; t < 24; t++) {
        // ---- prefetch tile t+1 into the other buffer ----
        if (t + 1 < 24) {
            const int tn = t + 1;
            const int frame = (tn >> 3) == 0 ? frame0 : (tn >> 3) == 1 ? frame1 : frame2;
            const int kb = (tn * 128) & (cN - 1);
            const size_t gof = (size_t)(frame * cN + kb + r0) * cInner + h * cD + d0;
            const float* kp = g_k + gof;
            const float* vp = g_v + gof;
            const uint32_t bo = sKV0 + (uint32_t)((tn & 1) * KVW) * 4;
#pragma unroll
            for (int i = 0; i < 10; i++) {
                cp_async16(bo + rowQ + i * 16, kp + i * 4);
                cp_async16(bo + rowV + i * 16, vp + i * 4);
            }
            cp_commit();
            cp_wait<1>();      // tile t complete
        } else {
            cp_wait<0>();
        }
        __syncthreads();

        const float* Ks = sm + SM_KV + (t & 1) * KVW;
        const float* Vs = Ks + 128 * QSP;

        // ---- S = Q K^T : 16 n-tiles x 10 k-steps (pure LDS+HMMA) ----
        float s[16][4];
#pragma unroll
        for (int n = 0; n < 16; n++)
#pragma unroll
            for (int j = 0; j < 4; j++) s[n][j] = 0.f;

#pragma unroll
        for (int n = 0; n < 16; n++) {
            const float* krow = Ks + (n * 8 + gid) * QSP + tig;
#pragma unroll
            for (int k = 0; k < 10; k++) {
                uint32_t b0 = __float_as_uint(krow[k * 8]);
                uint32_t b1 = __float_as_uint(krow[k * 8 + 4]);
                mma_tf32(s[n], qa[k], b0, b1);
            }
        }

        // ---- online softmax (rows live in-warp) ----
        float mx0 = -1e30f, mx1 = -1e30f;
#pragma unroll
        for (int n = 0; n < 16; n++) {
            mx0 = fmaxf(mx0, fmaxf(s[n][0], s[n][1]));
            mx1 = fmaxf(mx1, fmaxf(s[n][2], s[n][3]));
        }
        mx0 = fmaxf(mx0, __shfl_xor_sync(0xffffffffu, mx0, 1));
        mx0 = fmaxf(mx0, __shfl_xor_sync(0xffffffffu, mx0, 2));
        mx1 = fmaxf(mx1, __shfl_xor_sync(0xffffffffu, mx1, 1));
        mx1 = fmaxf(mx1, __shfl_xor_sync(0xffffffffu, mx1, 2));

        const float mn0 = fmaxf(mlo, mx0);
        const float mn1 = fmaxf(mhi, mx1);
        const float cf0 = __expf(mlo - mn0);
        const float cf1 = __expf(mhi - mn1);
        mlo = mn0; mhi = mn1;

        float rs0 = 0.f, rs1 = 0.f;
#pragma unroll
        for (int n = 0; n < 16; n++) {
            s[n][0] = __expf(s[n][0] - mn0); rs0 += s[n][0];
            s[n][1] = __expf(s[n][1] - mn0); rs0 += s[n][1];
            s[n][2] = __expf(s[n][2] - mn1); rs1 += s[n][2];
            s[n][3] = __expf(s[n][3] - mn1); rs1 += s[n][3];
        }
        rs0 += __shfl_xor_sync(0xffffffffu, rs0, 1);
        rs0 += __shfl_xor_sync(0xffffffffu, rs0, 2);
        rs1 += __shfl_xor_sync(0xffffffffu, rs1, 1);
        rs1 += __shfl_xor_sync(0xffffffffu, rs1, 2);
        llo = llo * cf0 + rs0;
        lhi = lhi * cf1 + rs1;

#pragma unroll
        for (int n = 0; n < 10; n++) {
            o[n][0] *= cf0; o[n][1] *= cf0;
            o[n][2] *= cf1; o[n][3] *= cf1;
        }

        // ---- O += P V : 16 k-tiles x 10 n-tiles ----
#pragma unroll
        for (int kt = 0; kt < 16; kt++) {
            float v00 = __shfl_sync(0xffffffffu, s[kt][0], sh1);
            float v01 = __shfl_sync(0xffffffffu, s[kt][1], sh1);
            float v02 = __shfl_sync(0xffffffffu, s[kt][0], sh2);
            float v03 = __shfl_sync(0xffffffffu, s[kt][1], sh2);
            float v10 = __shfl_sync(0xffffffffu, s[kt][2], sh1);
            float v11 = __shfl_sync(0xffffffffu, s[kt][3], sh1);
            float v12 = __shfl_sync(0xffffffffu, s[kt][2], sh2);
            float v13 = __shfl_sync(0xffffffffu, s[kt][3], sh2);
            uint32_t pa[4];
            pa[0] = tf32r(odd ? v01 : v00);
            pa[1] = tf32r(odd ? v11 : v10);
            pa[2] = tf32r(odd ? v03 : v02);
            pa[3] = tf32r(odd ? v13 : v12);

            const float* vrow0 = Vs + (kt * 8 + tig) * VSP + gid;
            const float* vrow1 = Vs + (kt * 8 + tig + 4) * VSP + gid;
#pragma unroll
            for (int n = 0; n < 10; n++) {
                uint32_t b0 = __float_as_uint(vrow0[n * 8]);
                uint32_t b1 = __float_as_uint(vrow1[n * 8]);
                mma_tf32(o[n], pa, b0, b1);
            }
        }
        __syncthreads();   // all warps done with buffer (t&1) before overwrite
    }

    // ---- epilogue ----
    const float inv0 = 1.f / llo;
    const float inv1 = 1.f / lhi;
    float* op0 = g_ao + (size_t)(b * cN + qt * 128 + m0 + gid) * cInner + h * cD;
    float* op1 = op0 + (size_t)8 * cInner;
#pragma unroll
    for (int n = 0; n < 10; n++) {
        *(float2*)(op0 + n * 8 + tig * 2) = make_float2(o[n][0] * inv0, o[n][1] * inv0);
        *(float2*)(op1 + n * 8 + tig * 2) = make_float2(o[n][2] * inv1, o[n][3] * inv1);
    }
}

// ---------------------------------------------------------------------------
extern "C" void kernel_launch(void* const* d_in, const int* in_sizes, int n_in,
                              void* d_out, int out_size)
{
    const float* x   = (const float*)d_in[0];
    const float* Wq  = (const float*)d_in[1];
    const float* Wk  = (const float*)d_in[2];
    const float* Wv  = (const float*)d_in[3];
    const float* Wo  = (const float*)d_in[4];
    const float* bo  = (const float*)d_in[5];
    const int*   ctx = (const int*)d_in[6];
    float* out = (float*)d_out;

    float* gq;  cudaGetSymbolAddress((void**)&gq, g_q);
    float* gk;  cudaGetSymbolAddress((void**)&gk, g_k);
    float* gv;  cudaGetSymbolAddress((void**)&gv, g_v);
    float* gao; cudaGetSymbolAddress((void**)&gao, g_ao);

    static bool attr_set = false;
    if (!attr_set) {
        cudaFuncSetAttribute(attn_mma,
                             cudaFuncAttributeMaxDynamicSharedMemorySize,
                             ATTN_SMEM);
        cudaFuncSetAttribute(gemm_tf32,
                             cudaFuncAttributeMaxDynamicSharedMemorySize,
                             GEMM_SMEM);
        attr_set = true;
    }

    // Fused QKV projections: gridDim.z picks (W, out) pair; epilogue
    // pre-rounds to tf32 (and pre-scales q by SCALE).
    gemm_tf32<<<dim3(cInner / 128, cM / 128, 3), 256, GEMM_SMEM>>>(
        x, Wq, Wk, Wv, gq, gk, gv, nullptr, cM, cInner, cC, SCALE, 1);

    attn_mma<<<dim3(8, 8, 8), 256, ATTN_SMEM>>>(ctx);

    // Output projection: no rounding, bias added.
    gemm_tf32<<<dim3(cC / 128, cM / 128, 1), 256, GEMM_SMEM>>>(
        gao, Wo, Wo, Wo, out, out, out, bo, cM, cC, cInner, 1.0f, 0);
}